// round 17
// baseline (speedup 1.0000x reference)
#include <cuda_runtime.h>
#include <cuda_bf16.h>
#include <math_constants.h>
#include <cstdint>

#define NB      8192
#define ND      128
#define TM      128
#define MARGIN  1.0f
#define NT      (NB / TM)            // 64
#define NTRI    (NT * (NT + 1) / 2)  // 2080

// smem tile: 128 rows x 136 halves (272B padded rows -> conflict-free ldmatrix)
#define RSTRIDE 136
#define BUFB    (128 * RSTRIDE * 2)  // 34816 bytes per operand buffer

// persistent double-buffer layout
#define OFF_SCR_R 0                  // float [128][4]
#define OFF_SCR_C 2048               // float [128][2]
#define BUF0      3072
#define BUFSZ     (2 * BUFB + 2048)  // A + B + hdr = 71680
#define OFF_A(s)   (BUF0 + (s) * BUFSZ)
#define OFF_B(s)   (OFF_A(s) + BUFB)
#define OFF_HDR(s) (OFF_B(s) + BUFB) // LI 0, LJ 512, SQI 1024, SQJ 1536
#define SMEM_SZ   (BUF0 + 2 * BUFSZ) // 146432 -> 1 CTA/SM

#define PPCAP   131072               // positive-pair entry capacity
#define PL_GRID 296                  // pairloss blocks
#define P1_GRID 148                  // persistent pass1 CTAs

// -------- scratch in device globals (no allocation allowed) --------
__device__ unsigned int g_hardest[NB];
__device__ float        g_sq[NB];
__device__ int          g_labels[NB];
__device__ float        g_total;
__device__ int          g_count;
__device__ int          g_done;
__device__ __nv_bfloat16 g_eb[NB * ND];          // bf16 embeddings
__device__ unsigned long long g_pp[PPCAP];       // packed (anchor<<32 | f32bits(d_pos))
__device__ int          g_pp_n;

__device__ __forceinline__ uint32_t smem_u32(const void* p) {
    uint32_t a;
    asm("{ .reg .u64 t; cvta.to.shared.u64 t, %1; cvt.u32.u64 %0, t; }" : "=r"(a) : "l"(p));
    return a;
}
__device__ __forceinline__ void cp_async16(uint32_t dst, const void* src) {
    asm volatile("cp.async.cg.shared.global [%0], [%1], 16;" :: "r"(dst), "l"(src) : "memory");
}
__device__ __forceinline__ void ldm_x4(uint32_t* r, uint32_t addr) {
    asm volatile("ldmatrix.sync.aligned.m8n8.x4.shared.b16 {%0,%1,%2,%3}, [%4];"
                 : "=r"(r[0]), "=r"(r[1]), "=r"(r[2]), "=r"(r[3]) : "r"(addr));
}
__device__ __forceinline__ void mma_bf16(float* c, const uint32_t* a, uint32_t b0, uint32_t b1) {
    asm volatile(
        "mma.sync.aligned.m16n8k16.row.col.f32.bf16.bf16.f32 "
        "{%0,%1,%2,%3}, {%4,%5,%6,%7}, {%8,%9}, {%0,%1,%2,%3};"
        : "+f"(c[0]), "+f"(c[1]), "+f"(c[2]), "+f"(c[3])
        : "r"(a[0]), "r"(a[1]), "r"(a[2]), "r"(a[3]), "r"(b0), "r"(b1));
}
__device__ __forceinline__ int labels_are_64(const int* p) {
    int ok = 1;
    #pragma unroll
    for (int q = 0; q < 32; ++q) ok &= (p[2 * q + 1] == 0);
    return ok;
}
// decode triangular index b = it*(it+1)/2 + jt, jt <= it
__device__ __forceinline__ void tri_decode(int b, int& it, int& jt) {
    it = (int)((sqrtf(8.0f * (float)b + 1.0f) - 1.0f) * 0.5f);
    while ((it + 1) * (it + 2) / 2 <= b) ++it;
    while (it * (it + 1) / 2 > b) --it;
    jt = b - it * (it + 1) / 2;
}
// issue cp.async group for tile (it, jt) into buffer slot s
__device__ __forceinline__ void prefetch_tile(uint32_t sbase, int s, int it, int jt, int t) {
    const char* srcA = (const char*)(g_eb + (size_t)(it * TM) * ND);
    const char* srcB = (const char*)(g_eb + (size_t)(jt * TM) * ND);
    uint32_t dA = sbase + OFF_A(s), dB = sbase + OFF_B(s);
    #pragma unroll
    for (int q = 0; q < 8; ++q) {
        int idx = t + q * 256;
        int row = idx >> 4, c16 = idx & 15;
        cp_async16(dA + row * (RSTRIDE * 2) + c16 * 16, srcA + (size_t)row * 256 + c16 * 16);
    }
    #pragma unroll
    for (int q = 0; q < 8; ++q) {
        int idx = t + q * 256;
        int row = idx >> 4, c16 = idx & 15;
        cp_async16(dB + row * (RSTRIDE * 2) + c16 * 16, srcB + (size_t)row * 256 + c16 * 16);
    }
    if (t < 128) {
        int reg = t >> 5, c = t & 31;
        const char* src;
        if      (reg == 0) src = (const char*)(g_labels + it * TM);
        else if (reg == 1) src = (const char*)(g_labels + jt * TM);
        else if (reg == 2) src = (const char*)(g_sq + it * TM);
        else               src = (const char*)(g_sq + jt * TM);
        cp_async16(sbase + OFF_HDR(s) + reg * 512 + c * 16, src + c * 16);
    }
    asm volatile("cp.async.commit_group;" ::: "memory");
}

// ---------------- kernel 0: init (sq, labels, bf16 convert, hardest=inf) ----------------
__global__ void __launch_bounds__(256) init_kernel(const float* __restrict__ E,
                                                   const void* __restrict__ labels_raw) {
    int warp = (blockIdx.x * blockDim.x + threadIdx.x) >> 5;  // 0..2047
    int lane = threadIdx.x & 31;
    int row0 = warp * 4;

    float4 e[4];
    #pragma unroll
    for (int r = 0; r < 4; ++r)
        e[r] = __ldg((const float4*)(E + (size_t)(row0 + r) * ND + lane * 4));

    #pragma unroll
    for (int r = 0; r < 4; ++r) {
        float s = e[r].x * e[r].x + e[r].y * e[r].y + e[r].z * e[r].z + e[r].w * e[r].w;
        #pragma unroll
        for (int o = 16; o > 0; o >>= 1) s += __shfl_xor_sync(0xffffffffu, s, o);
        __nv_bfloat16 b0[4] = {__float2bfloat16(e[r].x), __float2bfloat16(e[r].y),
                               __float2bfloat16(e[r].z), __float2bfloat16(e[r].w)};
        *(ushort4*)(g_eb + (size_t)(row0 + r) * ND + lane * 4) = *(ushort4*)b0;
        if (lane == 0) {
            g_sq[row0 + r] = s;
            g_hardest[row0 + r] = 0x7f800000u;  // +inf
        }
    }
    if (lane < 4) {
        int i = row0 + lane;
        const int* p32 = (const int*)labels_raw;
        g_labels[i] = labels_are_64(p32) ? (int)((const long long*)labels_raw)[i] : p32[i];
    }
    if (blockIdx.x == 0 && threadIdx.x == 0) {
        g_total = 0.0f; g_count = 0; g_pp_n = 0; g_done = 0;
    }
}

// ---------------- kernel 1: persistent double-buffered triangular GEMM + masked min ----------------
extern __shared__ char smem_raw[];
__global__ void __launch_bounds__(256, 1) pass1_kernel() {
    const int t    = threadIdx.x;
    const int wid  = t >> 5;
    const int lane = t & 31;
    const int wm   = wid >> 2;      // 0..1  (m half)
    const int wn   = wid & 3;       // 0..3  (n quarter)
    const int g    = lane >> 2;     // group
    const int qt   = lane & 3;      // thread in quad
    uint32_t sbase = smem_u32(smem_raw);

    int b = blockIdx.x;
    int it, jt;
    tri_decode(b, it, jt);
    prefetch_tile(sbase, 0, it, jt, t);
    int s = 0;

    while (b < NTRI) {
        int nb = b + (int)gridDim.x;
        int nit = 0, njt = 0;
        bool hasnext = (nb < NTRI);
        if (hasnext) {
            tri_decode(nb, nit, njt);
            prefetch_tile(sbase, s ^ 1, nit, njt, t);
            asm volatile("cp.async.wait_group 1;" ::: "memory");
        } else {
            asm volatile("cp.async.wait_group 0;" ::: "memory");
        }
        __syncthreads();

        const int diag = (it == jt);
        const uint32_t hdr = sbase + OFF_HDR(s);
        const char* hdrp = smem_raw + OFF_HDR(s);

        // ldmatrix addressing (proven layout)
        uint32_t pA = sbase + OFF_A(s) +
                      ((wm * 64 + (lane & 15)) * RSTRIDE + (lane >> 4) * 8) * 2;
        uint32_t pB = sbase + OFF_B(s) +
                      ((wn * 32 + ((lane >> 4) * 8) + (lane & 7)) * RSTRIDE +
                       ((lane >> 3) & 1) * 8) * 2;
        (void)hdr;

        float acc[4][4][4];
        #pragma unroll
        for (int mi = 0; mi < 4; ++mi)
            #pragma unroll
            for (int ni = 0; ni < 4; ++ni)
                #pragma unroll
                for (int c = 0; c < 4; ++c) acc[mi][ni][c] = 0.0f;

        #pragma unroll
        for (int ks = 0; ks < 8; ++ks) {
            uint32_t afr[4][4], bfr[2][4];
            #pragma unroll
            for (int mi = 0; mi < 4; ++mi)
                ldm_x4(afr[mi], pA + mi * (16 * RSTRIDE * 2) + ks * 32);
            #pragma unroll
            for (int np = 0; np < 2; ++np)
                ldm_x4(bfr[np], pB + np * (16 * RSTRIDE * 2) + ks * 32);
            #pragma unroll
            for (int mi = 0; mi < 4; ++mi)
                #pragma unroll
                for (int ni = 0; ni < 4; ++ni)
                    mma_bf16(acc[mi][ni], afr[mi],
                             bfr[ni >> 1][(ni & 1) * 2], bfr[ni >> 1][(ni & 1) * 2 + 1]);
        }

        // ---------------- epilogue: masked min + mask-deferred harvest ----------------
        int   liR[4][2];  float sqiR[4][2];
        int   ljC[4][2];  float sqjC[4][2];
        #pragma unroll
        for (int mi = 0; mi < 4; ++mi)
            #pragma unroll
            for (int h = 0; h < 2; ++h) {
                int r = wm * 64 + mi * 16 + h * 8 + g;
                liR[mi][h]  = *(const int*)  (hdrp + r * 4);           // LI
                sqiR[mi][h] = *(const float*)(hdrp + 1024 + r * 4);    // SQI
            }
        #pragma unroll
        for (int ni = 0; ni < 4; ++ni)
            #pragma unroll
            for (int cb = 0; cb < 2; ++cb) {
                int c = wn * 32 + ni * 8 + qt * 2 + cb;
                ljC[ni][cb]  = *(const int*)  (hdrp + 512 + c * 4);    // LJ
                sqjC[ni][cb] = *(const float*)(hdrp + 1536 + c * 4);   // SQJ
            }

        float rowmin[4][2], colmin[4][2];
        #pragma unroll
        for (int x = 0; x < 4; ++x)
            #pragma unroll
            for (int y = 0; y < 2; ++y) { rowmin[x][y] = CUDART_INF_F; colmin[x][y] = CUDART_INF_F; }

        unsigned long long pmask = 0ull;
        #pragma unroll
        for (int mi = 0; mi < 4; ++mi)
            #pragma unroll
            for (int ni = 0; ni < 4; ++ni)
                #pragma unroll
                for (int h = 0; h < 2; ++h)
                    #pragma unroll
                    for (int cb = 0; cb < 2; ++cb) {
                        float d = fmaf(-2.0f, acc[mi][ni][h * 2 + cb],
                                       sqiR[mi][h] + sqjC[ni][cb]);
                        bool pos = (ljC[ni][cb] == liR[mi][h]);
                        pmask |= ((unsigned long long)pos) << (mi * 16 + ni * 4 + h * 2 + cb);
                        float m = pos ? CUDART_INF_F : d;
                        rowmin[mi][h]  = fminf(rowmin[mi][h], m);
                        colmin[ni][cb] = fminf(colmin[ni][cb], m);
                    }

        // deferred harvest (rare): recompute dot in fp32 from resident smem tiles
        while (pmask) {
            int site = __ffsll(pmask) - 1;
            pmask &= pmask - 1;
            int cb = site & 1, h = (site >> 1) & 1, ni = (site >> 2) & 3, mi = site >> 4;
            int r = wm * 64 + mi * 16 + h * 8 + g;
            int c = wn * 32 + ni * 8 + qt * 2 + cb;
            int R = it * TM + r, C = jt * TM + c;
            if (diag && R <= C) continue;
            const __nv_bfloat16* ar = (const __nv_bfloat16*)(smem_raw + OFF_A(s) + r * RSTRIDE * 2);
            const __nv_bfloat16* br = (const __nv_bfloat16*)(smem_raw + OFF_B(s) + c * RSTRIDE * 2);
            float dot = 0.0f;
            #pragma unroll 16
            for (int k = 0; k < ND; k += 2) {
                float2 a2 = __bfloat1622float2(*(const __nv_bfloat162*)(ar + k));
                float2 b2 = __bfloat1622float2(*(const __nv_bfloat162*)(br + k));
                dot = fmaf(a2.x, b2.x, dot);
                dot = fmaf(a2.y, b2.y, dot);
            }
            float sqi = *(const float*)(hdrp + 1024 + r * 4);
            float sqj = *(const float*)(hdrp + 1536 + c * 4);
            unsigned db = __float_as_uint(fmaxf(fmaf(-2.0f, dot, sqi + sqj), 0.0f));
            int pos2 = atomicAdd(&g_pp_n, 2);
            if (pos2 <= PPCAP - 2) {
                g_pp[pos2]     = ((unsigned long long)(unsigned)R << 32) | db;
                g_pp[pos2 + 1] = ((unsigned long long)(unsigned)C << 32) | db;
            }
        }

        // scratch + combine
        #pragma unroll
        for (int mi = 0; mi < 4; ++mi)
            #pragma unroll
            for (int h = 0; h < 2; ++h) {
                float v = rowmin[mi][h];
                v = fminf(v, __shfl_xor_sync(0xffffffffu, v, 1));
                v = fminf(v, __shfl_xor_sync(0xffffffffu, v, 2));
                if (qt == 0) {
                    int r = wm * 64 + mi * 16 + h * 8 + g;
                    *(float*)(smem_raw + OFF_SCR_R + (r * 4 + wn) * 4) = v;
                }
            }
        #pragma unroll
        for (int ni = 0; ni < 4; ++ni)
            #pragma unroll
            for (int cb = 0; cb < 2; ++cb) {
                float v = colmin[ni][cb];
                v = fminf(v, __shfl_xor_sync(0xffffffffu, v, 4));
                v = fminf(v, __shfl_xor_sync(0xffffffffu, v, 8));
                v = fminf(v, __shfl_xor_sync(0xffffffffu, v, 16));
                if (lane < 4) {
                    int c = wn * 32 + ni * 8 + qt * 2 + cb;
                    *(float*)(smem_raw + OFF_SCR_C + (c * 2 + wm) * 4) = v;
                }
            }
        __syncthreads();

        if (t < 128) {
            const float* sr = (const float*)(smem_raw + OFF_SCR_R) + t * 4;
            float m = fminf(fminf(sr[0], sr[1]), fminf(sr[2], sr[3]));
            atomicMin(&g_hardest[it * TM + t], __float_as_uint(fmaxf(m, 0.0f)));
        } else {
            int c = t - 128;
            const float* sc = (const float*)(smem_raw + OFF_SCR_C) + c * 2;
            float m = fminf(sc[0], sc[1]);
            atomicMin(&g_hardest[jt * TM + c], __float_as_uint(fmaxf(m, 0.0f)));
        }
        __syncthreads();   // scr + buffer reuse safety before next iteration

        b = nb; it = nit; jt = njt; s ^= 1;
    }
}

// ---------------- kernel 2: per-entry triplet loss, block-reduced + last-block finalize ----------------
__global__ void __launch_bounds__(256) pairloss_kernel(float* out, int out_n) {
    __shared__ float s_ls[8];
    __shared__ int   s_lc[8];
    int n = g_pp_n;
    if (n > PPCAP) n = PPCAP;
    int lane  = threadIdx.x & 31;
    int warpl = threadIdx.x >> 5;

    float ls = 0.0f;
    int   lc = 0;
    for (int i = blockIdx.x * blockDim.x + threadIdx.x; i < n;
         i += gridDim.x * blockDim.x) {
        unsigned long long e = g_pp[i];
        int   a  = (int)(e >> 32);
        float dp = __uint_as_float((unsigned)e);
        float hn = __uint_as_float(g_hardest[a]);   // +inf => no negative
        if (hn < dp) {
            ls += fmaxf(dp - hn + MARGIN, 0.0f);
            lc += 1;
        }
    }
    #pragma unroll
    for (int o = 16; o > 0; o >>= 1) {
        ls += __shfl_xor_sync(0xffffffffu, ls, o);
        lc += __shfl_xor_sync(0xffffffffu, lc, o);
    }
    if (lane == 0) { s_ls[warpl] = ls; s_lc[warpl] = lc; }
    __syncthreads();
    if (threadIdx.x == 0) {
        float bls = 0.0f;
        int   blc = 0;
        #pragma unroll
        for (int w = 0; w < 8; ++w) { bls += s_ls[w]; blc += s_lc[w]; }
        if (blc) {
            atomicAdd(&g_total, bls);
            atomicAdd(&g_count, blc);
        }
    }

    // last-block finalization
    __syncthreads();
    __threadfence();
    __shared__ int is_last;
    if (threadIdx.x == 0)
        is_last = (atomicAdd(&g_done, 1) == (int)gridDim.x - 1);
    __syncthreads();
    if (is_last) {
        for (int i = threadIdx.x; i < out_n; i += blockDim.x) {
            if (i == 0) {
                int c = g_count;
                out[0] = g_total / (float)(c > 0 ? c : 1);
            } else if (i == 1) {
                out[1] = (float)g_count;
            } else {
                out[i] = 0.0f;
            }
        }
    }
}

extern "C" void kernel_launch(void* const* d_in, const int* in_sizes, int n_in,
                              void* d_out, int out_size) {
    const float* E   = (const float*)d_in[0];
    const void*  lab = d_in[1];

    cudaFuncSetAttribute(pass1_kernel, cudaFuncAttributeMaxDynamicSharedMemorySize, SMEM_SZ);

    init_kernel<<<NB / 32, 256>>>(E, lab);          // 256 blocks, 4 rows/warp
    pass1_kernel<<<P1_GRID, 256, SMEM_SZ>>>();
    pairloss_kernel<<<PL_GRID, 256>>>((float*)d_out, out_size);
}